// round 4
// baseline (speedup 1.0000x reference)
#include <cuda_runtime.h>
#include <stdint.h>

// Quantum 2x2 gate apply on qubit axis TARGET=5 of state (2,)^24 x (4,) f32.
// Persistent single-wave grid-stride kernel: grid = 148 SMs * 8 CTAs,
// eliminating wave transitions. float4 units; target stride = 2^18 f4 units.

static constexpr int SHIFT = 18;                   // target stride in float4 units
static constexpr long long NPAIRS = 1LL << 23;     // pairs of float4
static constexpr int NSM = 148;
static constexpr int CTAS_PER_SM = 8;
static constexpr int THREADS = 256;

__global__ __launch_bounds__(THREADS, CTAS_PER_SM)
void gate_apply_kernel(const float4* __restrict__ state,
                       const float*  __restrict__ pauli,
                       float4* __restrict__ out)
{
    const float p00 = pauli[0];
    const float p01 = pauli[1];
    const float p10 = pauli[2];
    const float p11 = pauli[3];

    const long long stride = (long long)gridDim.x * blockDim.x;
    long long v = (long long)blockIdx.x * blockDim.x + threadIdx.x;

    for (; v < NPAIRS; v += stride) {
        long long low  = v & ((1LL << SHIFT) - 1);
        long long idx0 = ((v >> SHIFT) << (SHIFT + 1)) | low;
        long long idx1 = idx0 + (1LL << SHIFT);

        float4 s0 = state[idx0];
        float4 s1 = state[idx1];

        float4 o0, o1;
        o0.x = p00 * s0.x + p01 * s1.x;
        o0.y = p00 * s0.y + p01 * s1.y;
        o0.z = p00 * s0.z + p01 * s1.z;
        o0.w = p00 * s0.w + p01 * s1.w;

        o1.x = p10 * s0.x + p11 * s1.x;
        o1.y = p10 * s0.y + p11 * s1.y;
        o1.z = p10 * s0.z + p11 * s1.z;
        o1.w = p10 * s0.w + p11 * s1.w;

        out[idx0] = o0;
        out[idx1] = o1;
    }
}

extern "C" void kernel_launch(void* const* d_in, const int* in_sizes, int n_in,
                              void* d_out, int out_size)
{
    const float4* state = (const float4*)d_in[0];
    const float*  pauli = (const float*)d_in[1];
    float4* out = (float4*)d_out;

    gate_apply_kernel<<<NSM * CTAS_PER_SM, THREADS>>>(state, pauli, out);
}

// round 5
// speedup vs baseline: 1.1054x; 1.1054x over previous
#include <cuda_runtime.h>
#include <stdint.h>

// Quantum 2x2 gate apply on qubit axis TARGET=5 of state (2,)^24 x (4,) f32.
// Best-measured shape (R1): one float4-pair per thread, fully coalesced,
// flat grid. Polished with 32-bit index arithmetic (all indices < 2^24).

static constexpr uint32_t SHIFT  = 18u;            // target stride in float4 units
static constexpr uint32_t NPAIRS = 1u << 23;       // 8,388,608 pairs

__global__ __launch_bounds__(256)
void gate_apply_kernel(const float4* __restrict__ state,
                       const float*  __restrict__ pauli,
                       float4* __restrict__ out)
{
    uint32_t v = blockIdx.x * blockDim.x + threadIdx.x;   // grid exactly covers NPAIRS

    const float p00 = pauli[0];
    const float p01 = pauli[1];
    const float p10 = pauli[2];
    const float p11 = pauli[3];

    uint32_t low  = v & ((1u << SHIFT) - 1u);
    uint32_t idx0 = ((v >> SHIFT) << (SHIFT + 1u)) | low;  // target bit = 0
    uint32_t idx1 = idx0 + (1u << SHIFT);                  // target bit = 1

    float4 s0 = state[idx0];
    float4 s1 = state[idx1];

    float4 o0, o1;
    o0.x = p00 * s0.x + p01 * s1.x;
    o0.y = p00 * s0.y + p01 * s1.y;
    o0.z = p00 * s0.z + p01 * s1.z;
    o0.w = p00 * s0.w + p01 * s1.w;

    o1.x = p10 * s0.x + p11 * s1.x;
    o1.y = p10 * s0.y + p11 * s1.y;
    o1.z = p10 * s0.z + p11 * s1.z;
    o1.w = p10 * s0.w + p11 * s1.w;

    out[idx0] = o0;
    out[idx1] = o1;
}

extern "C" void kernel_launch(void* const* d_in, const int* in_sizes, int n_in,
                              void* d_out, int out_size)
{
    const float4* state = (const float4*)d_in[0];
    const float*  pauli = (const float*)d_in[1];
    float4* out = (float4*)d_out;

    const int threads = 256;
    const unsigned blocks = NPAIRS / threads;   // 32768, exact cover
    gate_apply_kernel<<<blocks, threads>>>(state, pauli, out);
}